// round 4
// baseline (speedup 1.0000x reference)
#include <cuda_runtime.h>
#include <cstdint>

#define Sn 512
#define Bn 64
#define Hd 1024
#define Ln 5

// scratch: emissions padded to stride 8 for aligned float4 staging
__device__ float g_emis[(size_t)Bn * Sn * 8];
__device__ float g_diff[Bn];

// ---------------------------------------------------------------------------
// Kernel 1: emissions = relu(feats @ W + b)   [HBM-bound: 128MB read]
// v2: warp owns 4 rows (was 8) + W transposed in smem read via LDS.128 +
// __launch_bounds__(256,3) -> ~80 regs -> 3 blocks/SM -> 24 warps/SM of MLP.
// grid 1024 blocks x 256 threads (8 warps x 4 rows = 32 rows/block).
// ---------------------------------------------------------------------------
__global__ __launch_bounds__(256, 3) void k_emis(const float* __restrict__ feats,
                                                 const float* __restrict__ W,
                                                 const float* __restrict__ bias) {
    __shared__ float sWT[Ln * Hd];  // transposed: sWT[j*Hd + k] = W[k*Ln + j]
    int tid = threadIdx.x;
    for (int i = tid; i < Ln * Hd; i += 256) {
        int j = i >> 10;        // i / Hd
        int k = i & (Hd - 1);   // i % Hd
        sWT[i] = W[k * Ln + j];
    }
    __syncthreads();

    int warp = tid >> 5, lane = tid & 31;
    int row0 = blockIdx.x * 32 + warp * 4;

    float acc[4][5];
#pragma unroll
    for (int r = 0; r < 4; r++)
#pragma unroll
        for (int j = 0; j < 5; j++) acc[r][j] = 0.0f;

    const float* fbase = feats + (size_t)row0 * Hd + lane * 4;

#pragma unroll
    for (int c = 0; c < 8; c++) {
        int k = c * 128 + lane * 4;

        float4 f[4];
#pragma unroll
        for (int r = 0; r < 4; r++)
            f[r] = *reinterpret_cast<const float4*>(fbase + (size_t)r * Hd + c * 128);

        float4 w[5];
#pragma unroll
        for (int j = 0; j < 5; j++)
            w[j] = *reinterpret_cast<const float4*>(&sWT[j * Hd + k]);

#pragma unroll
        for (int r = 0; r < 4; r++) {
#pragma unroll
            for (int j = 0; j < 5; j++) {
                float s = acc[r][j];
                s = fmaf(f[r].x, w[j].x, s);
                s = fmaf(f[r].y, w[j].y, s);
                s = fmaf(f[r].z, w[j].z, s);
                s = fmaf(f[r].w, w[j].w, s);
                acc[r][j] = s;
            }
        }
    }

#pragma unroll
    for (int r = 0; r < 4; r++) {
#pragma unroll
        for (int j = 0; j < 5; j++) {
            float v = acc[r][j];
            v += __shfl_xor_sync(0xffffffffu, v, 16);
            v += __shfl_xor_sync(0xffffffffu, v, 8);
            v += __shfl_xor_sync(0xffffffffu, v, 4);
            v += __shfl_xor_sync(0xffffffffu, v, 2);
            v += __shfl_xor_sync(0xffffffffu, v, 1);
            acc[r][j] = v;
        }
        if (lane < 5) {
            float e = acc[r][lane] + bias[lane];
            g_emis[(size_t)(row0 + r) * 8 + lane] = fmaxf(e, 0.0f);
        }
    }
}

// ---------------------------------------------------------------------------
// Kernel 2: CRF forward (prob-domain) + Viterbi + numerator + backtrack.
// One block (128 thr) per batch. warp0=forward, warp1=viterbi, warp2=numerator.
// Emissions staged to SMEM first; per-step loads are depth-2 pipelined LDS.
// ---------------------------------------------------------------------------
__global__ __launch_bounds__(128) void k_scan(const int* __restrict__ labels,
                                              const float* __restrict__ start_t,
                                              const float* __restrict__ end_t,
                                              const float* __restrict__ trans,
                                              const float* __restrict__ weights,
                                              float* __restrict__ out) {
    __shared__ float sh_e[Sn * 8];          // 16 KB
    __shared__ unsigned char sh_bp[Sn * 8]; // 4 KB backpointers
    __shared__ float sh_num;
    __shared__ float sh_logz;

    const int b = blockIdx.x;
    const int tid = threadIdx.x;

    // stage emissions for this batch into shared (float4, coalesced)
    {
        const float4* src = reinterpret_cast<const float4*>(g_emis + (size_t)b * Sn * 8);
        float4* dst = reinterpret_cast<float4*>(sh_e);
        for (int i = tid; i < Sn * 2; i += 128) dst[i] = src[i];
    }
    __syncthreads();

    const int warp = tid >> 5;
    const int lane = tid & 31;

    if (warp == 2) {
        // ---- numerator: gold path score with class weights ----
        const int* lab = labels + b * Sn;
        float acc = 0.0f;
        for (int t = lane; t < Sn; t += 32) {
            int l = lab[t];
            acc = fmaf(weights[l], sh_e[t * 8 + l], acc);
            if (t > 0) acc += trans[lab[t - 1] * Ln + l];
        }
#pragma unroll
        for (int o = 16; o; o >>= 1) acc += __shfl_xor_sync(0xffffffffu, acc, o);
        if (lane == 0) {
            acc += start_t[lab[0]] + end_t[lab[Sn - 1]];
            sh_num = acc;
        }
    } else if (warp == 0) {
        // ---- forward algorithm in probability domain ----
        const int jj = (lane < 5) ? lane : 0;
        const float T0 = __expf(trans[0 * Ln + jj]);
        const float T1 = __expf(trans[1 * Ln + jj]);
        const float T2 = __expf(trans[2 * Ln + jj]);
        const float T3 = __expf(trans[3 * Ln + jj]);
        const float T4 = __expf(trans[4 * Ln + jj]);

        float p = __expf(start_t[jj] + sh_e[0 * 8 + jj]);
        float logscale = 0.0f;

        float e_n1 = sh_e[1 * 8 + jj];   // e(t=1)
        float x_cur = __expf(e_n1);      // exp(e) for t=1
        float e_n2 = sh_e[2 * 8 + jj];   // e(t=2)

        for (int t = 1; t < Sn; t++) {
            float x = x_cur;                 // exp(e(t)), ready
            x_cur = __expf(e_n2);            // exp(e(t+1)); e_n2 loaded last iter
            float e_n3 = (t + 2 < Sn) ? sh_e[(t + 2) * 8 + jj] : 0.0f;

            float a0 = __shfl_sync(0xffffffffu, p, 0);
            float a1 = __shfl_sync(0xffffffffu, p, 1);
            float a2 = __shfl_sync(0xffffffffu, p, 2);
            float a3 = __shfl_sync(0xffffffffu, p, 3);
            float a4 = __shfl_sync(0xffffffffu, p, 4);

            float s = a0 * T0;
            s = fmaf(a1, T1, s);
            s = fmaf(a2, T2, s);
            s = fmaf(a3, T3, s);
            s = fmaf(a4, T4, s);

            if ((t & 7) == 0) {  // renormalize to keep fp32 in range
                float m = fmaxf(fmaxf(fmaxf(a0, a1), fmaxf(a2, a3)), a4);
                s = __fdividef(s, m);
                logscale += __logf(m);
            }
            p = s * x;
            e_n2 = e_n3;
        }

        float a0 = __shfl_sync(0xffffffffu, p, 0);
        float a1 = __shfl_sync(0xffffffffu, p, 1);
        float a2 = __shfl_sync(0xffffffffu, p, 2);
        float a3 = __shfl_sync(0xffffffffu, p, 3);
        float a4 = __shfl_sync(0xffffffffu, p, 4);
        if (lane == 0) {
            float s = a0 * __expf(end_t[0]);
            s = fmaf(a1, __expf(end_t[1]), s);
            s = fmaf(a2, __expf(end_t[2]), s);
            s = fmaf(a3, __expf(end_t[3]), s);
            s = fmaf(a4, __expf(end_t[4]), s);
            sh_logz = __logf(s) + logscale;
        }
    } else if (warp == 1) {
        // ---- Viterbi (max-plus) with backpointers ----
        const int jj = (lane < 5) ? lane : 0;
        const float T0 = trans[0 * Ln + jj];
        const float T1 = trans[1 * Ln + jj];
        const float T2 = trans[2 * Ln + jj];
        const float T3 = trans[3 * Ln + jj];
        const float T4 = trans[4 * Ln + jj];

        float v = start_t[jj] + sh_e[0 * 8 + jj];
        float e_n1 = sh_e[1 * 8 + jj];
        float e_n2 = sh_e[2 * 8 + jj];

        for (int t = 1; t < Sn; t++) {
            float e = e_n1;
            e_n1 = e_n2;
            e_n2 = (t + 2 < Sn) ? sh_e[(t + 2) * 8 + jj] : 0.0f;

            float a0 = __shfl_sync(0xffffffffu, v, 0);
            float a1 = __shfl_sync(0xffffffffu, v, 1);
            float a2 = __shfl_sync(0xffffffffu, v, 2);
            float a3 = __shfl_sync(0xffffffffu, v, 3);
            float a4 = __shfl_sync(0xffffffffu, v, 4);

            float best = a0 + T0;
            int bi = 0;
            float c;
            c = a1 + T1; if (c > best) { best = c; bi = 1; }
            c = a2 + T2; if (c > best) { best = c; bi = 2; }
            c = a3 + T3; if (c > best) { best = c; bi = 3; }
            c = a4 + T4; if (c > best) { best = c; bi = 4; }
            v = best + e;
            if (lane < 5) sh_bp[t * 8 + lane] = (unsigned char)bi;
        }

        float score = v + end_t[jj];
        float s0 = __shfl_sync(0xffffffffu, score, 0);
        float s1 = __shfl_sync(0xffffffffu, score, 1);
        float s2 = __shfl_sync(0xffffffffu, score, 2);
        float s3 = __shfl_sync(0xffffffffu, score, 3);
        float s4 = __shfl_sync(0xffffffffu, score, 4);
        __syncwarp();  // sh_bp visible to lane 0
        if (lane == 0) {
            int last = 0; float bb = s0;
            if (s1 > bb) { bb = s1; last = 1; }
            if (s2 > bb) { bb = s2; last = 2; }
            if (s3 > bb) { bb = s3; last = 3; }
            if (s4 > bb) { bb = s4; last = 4; }
            float* po = out + 1 + (size_t)b * Sn;
            int tag = last;
            po[Sn - 1] = (float)tag;
            for (int t = Sn - 2; t >= 0; t--) {
                tag = sh_bp[(t + 1) * 8 + tag];
                po[t] = (float)tag;
            }
        }
    }
    __syncthreads();
    if (tid == 0) g_diff[b] = sh_num - sh_logz;
}

// ---------------------------------------------------------------------------
// Kernel 3: loss = -sum(num_b - logz_b) / (B*S)
// ---------------------------------------------------------------------------
__global__ void k_final(float* __restrict__ out) {
    int lane = threadIdx.x;
    float acc = g_diff[lane] + g_diff[lane + 32];
#pragma unroll
    for (int o = 16; o; o >>= 1) acc += __shfl_xor_sync(0xffffffffu, acc, o);
    if (lane == 0) out[0] = -acc * (1.0f / (float)(Bn * Sn));
}

extern "C" void kernel_launch(void* const* d_in, const int* in_sizes, int n_in,
                              void* d_out, int out_size) {
    const float* feats   = (const float*)d_in[0];
    const int*   labels  = (const int*)  d_in[1];
    // d_in[2] = mask (all ones in this problem; reference requires mask[:,0] on)
    const float* W       = (const float*)d_in[3];
    const float* bias    = (const float*)d_in[4];
    const float* start_t = (const float*)d_in[5];
    const float* end_t   = (const float*)d_in[6];
    const float* trans   = (const float*)d_in[7];
    const float* weights = (const float*)d_in[8];
    float* out = (float*)d_out;

    k_emis<<<1024, 256>>>(feats, W, bias);
    k_scan<<<Bn, 128>>>(labels, start_t, end_t, trans, weights, out);
    k_final<<<1, 32>>>(out);
}

// round 5
// speedup vs baseline: 1.3798x; 1.3798x over previous
#include <cuda_runtime.h>
#include <cstdint>

#define Sn 512
#define Bn 64
#define Hd 1024
#define Ln 5

// scratch: emissions padded to stride 8 for aligned float4 staging
__device__ float g_emis[(size_t)Bn * Sn * 8];
__device__ float g_diff[Bn];

// ---------------------------------------------------------------------------
// Kernel 1: emissions = relu(feats @ W + b)   [HBM-bound: 128MB read]
// v3: double-buffered chunk prefetch (8 LDG.128 in flight per warp),
// 2 blocks/SM (16 warps -> 64KB outstanding loads per SM).
// grid 1024 x 256 threads; warp owns 4 rows.
// ---------------------------------------------------------------------------
__global__ __launch_bounds__(256, 2) void k_emis(const float* __restrict__ feats,
                                                 const float* __restrict__ W,
                                                 const float* __restrict__ bias) {
    __shared__ float sWT[Ln * Hd];  // transposed: sWT[j*Hd + k] = W[k*Ln + j]
    int tid = threadIdx.x;
    for (int i = tid; i < Ln * Hd; i += 256) {
        int j = i >> 10;
        int k = i & (Hd - 1);
        sWT[i] = W[k * Ln + j];
    }
    __syncthreads();

    int warp = tid >> 5, lane = tid & 31;
    int row0 = blockIdx.x * 32 + warp * 4;

    float acc[4][5];
#pragma unroll
    for (int r = 0; r < 4; r++)
#pragma unroll
        for (int j = 0; j < 5; j++) acc[r][j] = 0.0f;

    const float* fbase = feats + (size_t)row0 * Hd + lane * 4;

    float4 f[4], fn[4];
#pragma unroll
    for (int r = 0; r < 4; r++)
        f[r] = *reinterpret_cast<const float4*>(fbase + (size_t)r * Hd);

#pragma unroll
    for (int c = 0; c < 8; c++) {
        // prefetch next chunk before this chunk's FMA block
        if (c < 7) {
#pragma unroll
            for (int r = 0; r < 4; r++)
                fn[r] = *reinterpret_cast<const float4*>(fbase + (size_t)r * Hd + (c + 1) * 128);
        }
        int k = c * 128 + lane * 4;
        float4 w[5];
#pragma unroll
        for (int j = 0; j < 5; j++)
            w[j] = *reinterpret_cast<const float4*>(&sWT[j * Hd + k]);

#pragma unroll
        for (int r = 0; r < 4; r++) {
#pragma unroll
            for (int j = 0; j < 5; j++) {
                float s = acc[r][j];
                s = fmaf(f[r].x, w[j].x, s);
                s = fmaf(f[r].y, w[j].y, s);
                s = fmaf(f[r].z, w[j].z, s);
                s = fmaf(f[r].w, w[j].w, s);
                acc[r][j] = s;
            }
        }
#pragma unroll
        for (int r = 0; r < 4; r++) f[r] = fn[r];
    }

#pragma unroll
    for (int r = 0; r < 4; r++) {
#pragma unroll
        for (int j = 0; j < 5; j++) {
            float v = acc[r][j];
            v += __shfl_xor_sync(0xffffffffu, v, 16);
            v += __shfl_xor_sync(0xffffffffu, v, 8);
            v += __shfl_xor_sync(0xffffffffu, v, 4);
            v += __shfl_xor_sync(0xffffffffu, v, 2);
            v += __shfl_xor_sync(0xffffffffu, v, 1);
            acc[r][j] = v;
        }
        if (lane < 5) {
            float e = acc[r][lane] + bias[lane];
            g_emis[(size_t)(row0 + r) * 8 + lane] = fmaxf(e, 0.0f);
        }
    }
}

// ---------------------------------------------------------------------------
// Kernel 2 v2: one block (512 thr = 16 warps) per batch.
//   warp 0      : sequential Viterbi (bit-exact vs reference), stores bp bytes
//   warp 1      : numerator, then (after named bar 1) forward serial combine
//   warps 8-15  : forward partition fn as 8 chunked 5x5 prob-domain matrix
//                 products (64 steps each, 25 lanes), hidden under Viterbi
//   all 16 warps: chunked-EXACT parallel backtrack (integer bp composition)
// ---------------------------------------------------------------------------
__global__ __launch_bounds__(512) void k_scan(const int* __restrict__ labels,
                                              const float* __restrict__ start_t,
                                              const float* __restrict__ end_t,
                                              const float* __restrict__ trans,
                                              const float* __restrict__ weights,
                                              float* __restrict__ out) {
    __shared__ float sh_e[Sn * 8];            // 16 KB emissions
    __shared__ float sh_x[Sn * 8];            // 16 KB exp(emissions)
    __shared__ unsigned char sh_bp[Sn * 8];   // 4 KB Viterbi backpointers
    __shared__ unsigned char sh_cand[16 * 5 * 32]; // candidate paths per chunk
    __shared__ unsigned char sh_map[16 * 8];  // chunk tag maps
    __shared__ int sh_exit[16];               // chunk exit tags
    __shared__ float sh_fwdM[8][25];          // fwd chunk matrices
    __shared__ float sh_fwdS[8];              // fwd chunk logscales
    __shared__ float sh_num, sh_logz;
    __shared__ int sh_last;

    const int b = blockIdx.x;
    const int tid = threadIdx.x;
    const int warp = tid >> 5;
    const int lane = tid & 31;

    // ---- stage emissions + exp(emissions) into shared ----
    {
        const float4* src = reinterpret_cast<const float4*>(g_emis + (size_t)b * Sn * 8);
        float4* de = reinterpret_cast<float4*>(sh_e);
        float4* dx = reinterpret_cast<float4*>(sh_x);
        for (int i = tid; i < Sn * 2; i += 512) {
            float4 v = src[i];
            de[i] = v;
            float4 xv;
            xv.x = __expf(v.x); xv.y = __expf(v.y);
            xv.z = __expf(v.z); xv.w = __expf(v.w);
            dx[i] = xv;
        }
    }
    __syncthreads();

    if (warp == 0) {
        // ================= sequential Viterbi (exact) =================
        const int jj = (lane < 5) ? lane : 0;
        const float T0 = trans[0 * Ln + jj];
        const float T1 = trans[1 * Ln + jj];
        const float T2 = trans[2 * Ln + jj];
        const float T3 = trans[3 * Ln + jj];
        const float T4 = trans[4 * Ln + jj];

        float v = start_t[jj] + sh_e[0 * 8 + jj];

        for (int t = 1; t < Sn; t++) {
            float e = sh_e[t * 8 + jj];  // independent of shfl chain; issues early

            float a0 = __shfl_sync(0xffffffffu, v, 0);
            float a1 = __shfl_sync(0xffffffffu, v, 1);
            float a2 = __shfl_sync(0xffffffffu, v, 2);
            float a3 = __shfl_sync(0xffffffffu, v, 3);
            float a4 = __shfl_sync(0xffffffffu, v, 4);

            float s0 = a0 + T0, s1 = a1 + T1, s2 = a2 + T2, s3 = a3 + T3, s4 = a4 + T4;
            // max tree (critical path), index recovery off-path via equality
            float m01 = fmaxf(s0, s1), m23 = fmaxf(s2, s3);
            float m03 = fmaxf(m01, m23);
            float best = fmaxf(m03, s4);
            int bi = (best == s0) ? 0 : (best == s1) ? 1 : (best == s2) ? 2
                   : (best == s3) ? 3 : 4;  // first-index ties, matches argmax
            if (lane < 5) sh_bp[t * 8 + lane] = (unsigned char)bi;
            v = best + e;
        }

        float score = v + end_t[jj];
        float s0 = __shfl_sync(0xffffffffu, score, 0);
        float s1 = __shfl_sync(0xffffffffu, score, 1);
        float s2 = __shfl_sync(0xffffffffu, score, 2);
        float s3 = __shfl_sync(0xffffffffu, score, 3);
        float s4 = __shfl_sync(0xffffffffu, score, 4);
        if (lane == 0) {
            float best = fmaxf(fmaxf(fmaxf(s0, s1), fmaxf(s2, s3)), s4);
            sh_last = (best == s0) ? 0 : (best == s1) ? 1 : (best == s2) ? 2
                    : (best == s3) ? 3 : 4;
        }
    } else if (warp == 1) {
        // ================= numerator =================
        const int* lab = labels + b * Sn;
        float acc = 0.0f;
        for (int t = lane; t < Sn; t += 32) {
            int l = lab[t];
            acc = fmaf(weights[l], sh_e[t * 8 + l], acc);
            if (t > 0) acc += trans[lab[t - 1] * Ln + l];
        }
#pragma unroll
        for (int o = 16; o; o >>= 1) acc += __shfl_xor_sync(0xffffffffu, acc, o);
        if (lane == 0) {
            acc += start_t[lab[0]] + end_t[lab[Sn - 1]];
            sh_num = acc;
        }
        // wait for fwd chunk matrices (warps 8-15); Viterbi warp NOT blocked
        asm volatile("bar.sync 1, 288;" ::: "memory");
        // ---- serial combine of 8 chunk matrices -> logZ ----
        if (lane == 0) {
            float a0 = __expf(start_t[0] + sh_e[0]);
            float a1 = __expf(start_t[1] + sh_e[1]);
            float a2 = __expf(start_t[2] + sh_e[2]);
            float a3 = __expf(start_t[3] + sh_e[3]);
            float a4 = __expf(start_t[4] + sh_e[4]);
            float ls = 0.0f;
#pragma unroll
            for (int c = 0; c < 8; c++) {
                const float* M = sh_fwdM[c];
                float n0 = a0*M[0] + a1*M[5] + a2*M[10] + a3*M[15] + a4*M[20];
                float n1 = a0*M[1] + a1*M[6] + a2*M[11] + a3*M[16] + a4*M[21];
                float n2 = a0*M[2] + a1*M[7] + a2*M[12] + a3*M[17] + a4*M[22];
                float n3 = a0*M[3] + a1*M[8] + a2*M[13] + a3*M[18] + a4*M[23];
                float n4 = a0*M[4] + a1*M[9] + a2*M[14] + a3*M[19] + a4*M[24];
                float m = fmaxf(fmaxf(fmaxf(n0, n1), fmaxf(n2, n3)), n4);
                float inv = __fdividef(1.0f, m);
                a0 = n0 * inv; a1 = n1 * inv; a2 = n2 * inv; a3 = n3 * inv; a4 = n4 * inv;
                ls += __logf(m) + sh_fwdS[c];
            }
            float z = a0 * __expf(end_t[0]) + a1 * __expf(end_t[1])
                    + a2 * __expf(end_t[2]) + a3 * __expf(end_t[3])
                    + a4 * __expf(end_t[4]);
            sh_logz = __logf(z) + ls;
        }
    } else if (warp >= 8) {
        // ================= forward: chunked 5x5 matrix products =================
        const int fc = warp - 8;            // chunk 0..7
        const int i = (lane < 25) ? (lane / 5) : 0;
        const int j = lane % 5;
        float eT0 = __expf(trans[0 * Ln + j]);
        float eT1 = __expf(trans[1 * Ln + j]);
        float eT2 = __expf(trans[2 * Ln + j]);
        float eT3 = __expf(trans[3 * Ln + j]);
        float eT4 = __expf(trans[4 * Ln + j]);

        float m = (i == j) ? 1.0f : 0.0f;   // identity
        float lsc = 0.0f;
        const int t0 = (fc == 0) ? 1 : 64 * fc;
        const int t1 = 64 * fc + 63;
        int cnt = 0;
        const int base = i * 5;
        for (int t = t0; t <= t1; t++) {
            float x = sh_x[t * 8 + j];
            float r0 = __shfl_sync(0xffffffffu, m, base + 0);
            float r1 = __shfl_sync(0xffffffffu, m, base + 1);
            float r2 = __shfl_sync(0xffffffffu, m, base + 2);
            float r3 = __shfl_sync(0xffffffffu, m, base + 3);
            float r4 = __shfl_sync(0xffffffffu, m, base + 4);
            float s = r0 * eT0;
            s = fmaf(r1, eT1, s);
            s = fmaf(r2, eT2, s);
            s = fmaf(r3, eT3, s);
            s = fmaf(r4, eT4, s);
            m = s * x;
            if ((++cnt & 7) == 0) {   // rescale to keep fp32 in range
                float mm = (lane < 25) ? m : 0.0f;
#pragma unroll
                for (int o = 16; o; o >>= 1)
                    mm = fmaxf(mm, __shfl_xor_sync(0xffffffffu, mm, o));
                m = __fdividef(m, mm);
                lsc += __logf(mm);
            }
        }
        if (lane < 25) sh_fwdM[fc][lane] = m;
        if (lane == 0) sh_fwdS[fc] = lsc;
        asm volatile("bar.sync 1, 288;" ::: "memory");
    }
    // warps 2-7 fall through

    __syncthreads();  // Viterbi bp + sh_last + sh_num + sh_logz all ready

    if (tid == 0) g_diff[b] = sh_num - sh_logz;

    // ================= chunked-exact parallel backtrack =================
    // each warp owns a 32-step chunk; lanes 0-4 compose candidate paths for
    // every possible chunk-exit tag (pure integer lookups -> bit-exact)
    {
        const int c = warp;  // 0..15
        if (lane < 5) {
            int tag = lane;
            const int tstart = (c == 0) ? 1 : 32 * c;
            for (int t = 32 * c + 31; t >= tstart; t--) {
                sh_cand[(c * 5 + lane) * 32 + (t - 32 * c)] = (unsigned char)tag;
                tag = sh_bp[t * 8 + tag];
            }
            if (c == 0) sh_cand[lane * 32 + 0] = (unsigned char)tag;
            sh_map[c * 8 + lane] = (unsigned char)tag;
        }
    }
    __syncthreads();

    if (tid == 0) {  // serial chain over 16 chunk maps (integer, exact)
        int tg = sh_last;
        sh_exit[15] = tg;
        for (int c = 15; c >= 1; c--) {
            tg = sh_map[c * 8 + tg];
            sh_exit[c - 1] = tg;
        }
    }
    __syncthreads();

    {
        const int c = warp;
        const int ex = sh_exit[c];
        out[1 + (size_t)b * Sn + c * 32 + lane] =
            (float)sh_cand[(c * 5 + ex) * 32 + lane];
    }
}

// ---------------------------------------------------------------------------
// Kernel 3: loss = -sum(num_b - logz_b) / (B*S)
// ---------------------------------------------------------------------------
__global__ void k_final(float* __restrict__ out) {
    int lane = threadIdx.x;
    float acc = g_diff[lane] + g_diff[lane + 32];
#pragma unroll
    for (int o = 16; o; o >>= 1) acc += __shfl_xor_sync(0xffffffffu, acc, o);
    if (lane == 0) out[0] = -acc * (1.0f / (float)(Bn * Sn));
}

extern "C" void kernel_launch(void* const* d_in, const int* in_sizes, int n_in,
                              void* d_out, int out_size) {
    const float* feats   = (const float*)d_in[0];
    const int*   labels  = (const int*)  d_in[1];
    // d_in[2] = mask (all ones; reference requires mask[:,0] on)
    const float* W       = (const float*)d_in[3];
    const float* bias    = (const float*)d_in[4];
    const float* start_t = (const float*)d_in[5];
    const float* end_t   = (const float*)d_in[6];
    const float* trans   = (const float*)d_in[7];
    const float* weights = (const float*)d_in[8];
    float* out = (float*)d_out;

    k_emis<<<1024, 256>>>(feats, W, bias);
    k_scan<<<Bn, 512>>>(labels, start_t, end_t, trans, weights, out);
    k_final<<<1, 32>>>(out);
}